// round 4
// baseline (speedup 1.0000x reference)
#include <cuda_runtime.h>
#include <math.h>

#define NS 1024
#define HD 256
#define XD 128
#define SPP 17   // k_pair smem row stride (float2 units): 34 words -> 2r mod 32 bank map, conflict-free
#define SG  33   // k_gemm smem row stride (float2 units): 66 words -> 2r mod 32 bank map

// scratch (device globals: no allocation allowed)
__device__ float g_xp[NS * HD];    // x @ Wx
__device__ float g_yp[NS * HD];    // y @ Wy + b1
__device__ double g_pe[2048];      // per-block exp-sum partials
__device__ double g_pd[2048];      // per-block diag partials
__device__ unsigned int g_cnt;

typedef unsigned long long u64;

__device__ __forceinline__ u64 pk2(float a, float b) {
    u64 r; asm("mov.b64 %0, {%1, %2};" : "=l"(r) : "f"(a), "f"(b)); return r;
}
__device__ __forceinline__ void up2(u64 v, float& a, float& b) {
    asm("mov.b64 {%0, %1}, %2;" : "=f"(a), "=f"(b) : "l"(v));
}
__device__ __forceinline__ u64 add2(u64 a, u64 b) {
    u64 r; asm("add.rn.f32x2 %0, %1, %2;" : "=l"(r) : "l"(a), "l"(b)); return r;
}
__device__ __forceinline__ u64 fma2(u64 a, u64 b, u64 c) {
    u64 r; asm("fma.rn.f32x2 %0, %1, %2, %3;" : "=l"(r) : "l"(a), "l"(b), "l"(c)); return r;
}

// Tiled GEMM: rows(2048 = x then y) x cols(256), K=128. 64x64 tiles, W in smem.
// grid 128 = 32 rowblocks x 4 colblocks. 256 threads, thread = 4r x 4c, k packed x2.
__global__ void __launch_bounds__(256) k_gemm(
    const float* __restrict__ x, const float* __restrict__ y,
    const float* __restrict__ W1, const float* __restrict__ b1)
{
    if (blockIdx.x == 0 && threadIdx.x == 0) g_cnt = 0u;

    __shared__ __align__(16) float2 xs[64 * SG];
    __shared__ __align__(16) float2 ws[64 * SG];

    int b = blockIdx.x;
    int rowblk = b >> 2;            // 0..31
    int colblk = b & 3;             // 0..3
    int isY = rowblk >> 4;
    int row0 = (rowblk & 15) << 6;
    int col0 = colblk << 6;
    const float* src = isY ? y : x;
    const float* W = W1 + isY * (XD * HD);
    int t = threadIdx.x;
    int tc = t & 15, tr = t >> 4;

    u64 acc[16];
    #pragma unroll
    for (int p = 0; p < 16; p++) acc[p] = 0ull;

    const float2* gsrc = (const float2*)src;   // 64 f2 per 128-float row
    float* wsf = (float*)ws;

    #pragma unroll 1
    for (int ch = 0; ch < 2; ch++) {
        __syncthreads();
        // x tile: 64 rows x 32 f2 (this k-chunk)
        #pragma unroll
        for (int p = 0; p < 8; p++) {
            int idx = t + p * 256;             // 0..2047
            int r = idx >> 5, k2 = idx & 31;
            xs[r * SG + k2] = gsrc[(row0 + r) * 64 + ch * 32 + k2];
        }
        // W tile transposed: ws[c][k] (64 cols x 64 k)
        #pragma unroll
        for (int p = 0; p < 16; p++) {
            int idx = t + p * 256;             // 0..4095
            int k = idx >> 6, c = idx & 63;
            wsf[c * (2 * SG) + k] = W[(ch * 64 + k) * HD + col0 + c];
        }
        __syncthreads();

        #pragma unroll 8
        for (int k2 = 0; k2 < 32; k2++) {
            u64 xv[4], wv[4];
            #pragma unroll
            for (int m = 0; m < 4; m++)
                xv[m] = *(const u64*)&xs[(tr + 16 * m) * SG + k2];
            #pragma unroll
            for (int m = 0; m < 4; m++)
                wv[m] = *(const u64*)&ws[(tc + 16 * m) * SG + k2];
            #pragma unroll
            for (int mr = 0; mr < 4; mr++)
                #pragma unroll
                for (int mc = 0; mc < 4; mc++)
                    acc[mr * 4 + mc] = fma2(xv[mr], wv[mc], acc[mr * 4 + mc]);
        }
    }

    float* dst = isY ? g_yp : g_xp;
    #pragma unroll
    for (int mc = 0; mc < 4; mc++) {
        int col = col0 + tc + 16 * mc;
        float bias = isY ? b1[col] : 0.0f;
        #pragma unroll
        for (int mr = 0; mr < 4; mr++) {
            float lo, hi; up2(acc[mr * 4 + mc], lo, hi);
            dst[(row0 + tr + 16 * mr) * HD + col] = lo + hi + bias;
        }
    }
}

// Pairwise kernel: 32(i) x 16(j) tile, 64 threads, 16 CTAs/SM -> all 2048 CTAs
// resident in one wave; many small warps hide LDS latency without reg pressure.
// Thread = 4i x 2j x (2k packed). Last block folds the final scalar.
__global__ void __launch_bounds__(64, 16) k_pair(
    const float* __restrict__ W2, const float* __restrict__ b2,
    float* __restrict__ out)
{
    __shared__ __align__(16) float2 xsh[16 * SPP];  // j rows (16)
    __shared__ __align__(16) float2 ysh[32 * SPP];  // i rows (32)
    __shared__ __align__(16) float2 wsh[128];       // all 256 W2 values, k-paired
    __shared__ float rr[4];
    __shared__ int flag_sh;

    int t = threadIdx.x;
    int tx = t & 7, ty = t >> 3;                    // tx: j, ty: i
    int jT = blockIdx.x << 4, iT = blockIdx.y << 5;

    wsh[t] = ((const float2*)W2)[t];
    wsh[t + 64] = ((const float2*)W2)[t + 64];

    const float4* gx = (const float4*)g_xp;         // 64 f4 per 256-float row
    const float4* gy = (const float4*)g_yp;

    u64 acc[8];
    #pragma unroll
    for (int p = 0; p < 8; p++) acc[p] = 0ull;

    #pragma unroll 1
    for (int ch = 0; ch < 8; ch++) {                // 32 k per chunk
        __syncthreads();
        // x: 16 rows x 8 f4 = 128 f4 -> 2/thread; y: 32 x 8 = 256 -> 4/thread
        #pragma unroll
        for (int p = 0; p < 2; p++) {
            int idx = t + p * 64;                   // 0..127
            int row = idx >> 3, c4 = idx & 7;
            float4 v = gx[(jT + row) * 64 + ch * 8 + c4];
            xsh[row * SPP + 2 * c4]     = make_float2(v.x, v.y);
            xsh[row * SPP + 2 * c4 + 1] = make_float2(v.z, v.w);
        }
        #pragma unroll
        for (int p = 0; p < 4; p++) {
            int idx = t + p * 64;                   // 0..255
            int row = idx >> 3, c4 = idx & 7;
            float4 v = gy[(iT + row) * 64 + ch * 8 + c4];
            ysh[row * SPP + 2 * c4]     = make_float2(v.x, v.y);
            ysh[row * SPP + 2 * c4 + 1] = make_float2(v.z, v.w);
        }
        __syncthreads();

        #pragma unroll
        for (int k2 = 0; k2 < 16; k2++) {           // 2 k per iter
            u64 w = *(const u64*)&wsh[ch * 16 + k2];
            u64 xv0 = *(const u64*)&xsh[tx * SPP + k2];
            u64 xv1 = *(const u64*)&xsh[(tx + 8) * SPP + k2];
            u64 yv[4];
            #pragma unroll
            for (int b4 = 0; b4 < 4; b4++)
                yv[b4] = *(const u64*)&ysh[(ty + 8 * b4) * SPP + k2];
            #pragma unroll
            for (int b4 = 0; b4 < 4; b4++) {
                u64 s0 = add2(xv0, yv[b4]);
                float l0, h0; up2(s0, l0, h0);
                l0 = fmaxf(l0, 0.0f); h0 = fmaxf(h0, 0.0f);
                acc[b4 * 2]     = fma2(pk2(l0, h0), w, acc[b4 * 2]);
                u64 s1 = add2(xv1, yv[b4]);
                float l1, h1; up2(s1, l1, h1);
                l1 = fmaxf(l1, 0.0f); h1 = fmaxf(h1, 0.0f);
                acc[b4 * 2 + 1] = fma2(pk2(l1, h1), w, acc[b4 * 2 + 1]);
            }
        }
    }

    // epilogue: per-pair dot -> exp-sum + diagonal capture
    float le = 0.0f, ld = 0.0f;
    #pragma unroll
    for (int b4 = 0; b4 < 4; b4++) {
        #pragma unroll
        for (int a = 0; a < 2; a++) {
            float lo, hi; up2(acc[b4 * 2 + a], lo, hi);
            float s = lo + hi;
            le += __expf(s);
            if (iT + ty + 8 * b4 == jT + tx + 8 * a) ld += s;
        }
    }

    #pragma unroll
    for (int o = 16; o > 0; o >>= 1) {
        le += __shfl_xor_sync(0xffffffffu, le, o);
        ld += __shfl_xor_sync(0xffffffffu, ld, o);
    }
    int wid = t >> 5, lane = t & 31;
    if (lane == 0) { rr[wid] = le; rr[2 + wid] = ld; }
    __syncthreads();
    if (t == 0) {
        int bid = blockIdx.y * 64 + blockIdx.x;     // grid (64, 32)
        g_pe[bid] = (double)(rr[0] + rr[1]);
        g_pd[bid] = (double)(rr[2] + rr[3]);
        __threadfence();
        unsigned int c = atomicAdd(&g_cnt, 1u);
        flag_sh = (c == 2047u) ? 1 : 0;
    }
    __syncthreads();

    if (flag_sh) {
        __threadfence();
        double se = 0.0, sd = 0.0;
        #pragma unroll
        for (int p = 0; p < 32; p++) {
            int i = t + p * 64;
            se += g_pe[i];
            sd += g_pd[i];
        }
        #pragma unroll
        for (int o = 16; o > 0; o >>= 1) {
            se += __shfl_xor_sync(0xffffffffu, se, o);
            sd += __shfl_xor_sync(0xffffffffu, sd, o);
        }
        __shared__ double dr[4];
        if (lane == 0) { dr[wid] = se; dr[2 + wid] = sd; }
        __syncthreads();
        if (t == 0) {
            double tse = dr[0] + dr[1];
            double tsd = dr[2] + dr[3];
            double bb = (double)b2[0];
            double lb = tsd / (double)NS + bb
                      - exp(bb - 1.0) * tse / ((double)NS * (double)NS);
            out[0] = (float)lb;
        }
    }
}

extern "C" void kernel_launch(void* const* d_in, const int* in_sizes, int n_in,
                              void* d_out, int out_size)
{
    (void)in_sizes; (void)n_in; (void)out_size;
    const float* x  = (const float*)d_in[0];
    const float* y  = (const float*)d_in[1];
    const float* W1 = (const float*)d_in[2];
    const float* b1 = (const float*)d_in[3];
    const float* W2 = (const float*)d_in[4];
    const float* b2 = (const float*)d_in[5];

    k_gemm<<<128, 256>>>(x, y, W1, b1);
    k_pair<<<dim3(64, 32), 64>>>(W2, b2, (float*)d_out);
}

// round 5
// speedup vs baseline: 1.0350x; 1.0350x over previous
#include <cuda_runtime.h>
#include <math.h>

#define NS 1024
#define HD 256
#define XD 128
#define TI 64            // i rows per tile (y side)
#define TJ 32            // j rows per tile (x side)
#define NTILE 512        // (1024/TI)*(1024/TJ)
#define NCTA 296         // 148 SMs * 2 CTAs -- must ALL be co-resident
#define KC 32            // k per chunk
#define NCH 8            // 256/KC
#define SW 36            // smem row stride in floats (LDS.128 conflict-free)

// device scratch (no allocations allowed)
__device__ __align__(16) float g_xp[NS * HD];   // x @ Wx
__device__ __align__(16) float g_yp[NS * HD];   // y @ Wy + b1
__device__ double g_pe[NTILE];
__device__ double g_pd[NTILE];
__device__ unsigned int c_bar;    // phase barrier   (0 at launch start, reset by final CTA)
__device__ unsigned int c_steal;  // tile counter    (ditto)
__device__ unsigned int c_done;   // completion ctr  (ditto)

typedef unsigned long long u64;

__device__ __forceinline__ u64 pk2(float a, float b) {
    u64 r; asm("mov.b64 %0, {%1, %2};" : "=l"(r) : "f"(a), "f"(b)); return r;
}
__device__ __forceinline__ void up2(u64 v, float& a, float& b) {
    asm("mov.b64 {%0, %1}, %2;" : "=f"(a), "=f"(b) : "l"(v));
}
__device__ __forceinline__ u64 add2(u64 a, u64 b) {
    u64 r; asm("add.rn.f32x2 %0, %1, %2;" : "=l"(r) : "l"(a), "l"(b)); return r;
}
__device__ __forceinline__ u64 fma2(u64 a, u64 b, u64 c) {
    u64 r; asm("fma.rn.f32x2 %0, %1, %2, %3;" : "=l"(r) : "l"(a), "l"(b), "l"(c)); return r;
}
__device__ __forceinline__ void cpa16(float* dst_smem, const float* src_gmem) {
    unsigned s = (unsigned)__cvta_generic_to_shared(dst_smem);
    asm volatile("cp.async.ca.shared.global [%0], [%1], 16;" :: "r"(s), "l"(src_gmem));
}

__global__ void __launch_bounds__(256, 2) k_fused(
    const float* __restrict__ x, const float* __restrict__ y,
    const float* __restrict__ W1, const float* __restrict__ b1,
    const float* __restrict__ W2, const float* __restrict__ b2,
    float* __restrict__ out)
{
    __shared__ __align__(16) float xs[128 * 10];          // phase 1: [k][r], 8 rows
    __shared__ __align__(16) float xbuf[2][TJ * SW];      // phase 2: j rows
    __shared__ __align__(16) float ybuf[2][TI * SW];      // phase 2: i rows
    __shared__ __align__(16) float wsh[HD];
    __shared__ float rr[16];
    __shared__ double dr[16];
    __shared__ unsigned int idsh;
    __shared__ int donesh;

    int t = threadIdx.x;
    int cta = blockIdx.x;

    // ---------------- Phase 1: projections (CTAs 0..255; 8 rows each) ----------------
    if (cta < 256) {
        int isY = cta >> 7;
        int row0 = (cta & 127) << 3;
        const float* src = isY ? y : x;
        const float* W = W1 + isY * (XD * HD);

        #pragma unroll
        for (int p = 0; p < 4; p++) {
            int idx = t + p * 256;          // 0..1023
            int r = idx >> 7, k = idx & 127;
            xs[k * 10 + r] = src[(row0 + r) * XD + k];
        }
        __syncthreads();

        u64 acc[4];
        #pragma unroll
        for (int m = 0; m < 4; m++) acc[m] = 0ull;

        #pragma unroll 8
        for (int k = 0; k < 128; k++) {
            float w = W[k * HD + t];
            u64 wd = pk2(w, w);
            #pragma unroll
            for (int m = 0; m < 4; m++)
                acc[m] = fma2(*(const u64*)&xs[k * 10 + 2 * m], wd, acc[m]);
        }

        float bias = isY ? b1[t] : 0.0f;
        float* dst = isY ? g_yp : g_xp;
        #pragma unroll
        for (int m = 0; m < 4; m++) {
            float v0, v1; up2(acc[m], v0, v1);
            dst[(row0 + 2 * m)     * HD + t] = v0 + bias;
            dst[(row0 + 2 * m + 1) * HD + t] = v1 + bias;
        }
    }

    // ---------------- device-wide barrier ----------------
    __threadfence();
    __syncthreads();
    if (t == 0) {
        atomicAdd(&c_bar, 1u);
        while (atomicAdd(&c_bar, 0u) < (unsigned)NCTA) __nanosleep(64);
    }
    __syncthreads();
    __threadfence();

    // ---------------- Phase 2: pairwise tiles via work stealing ----------------
    wsh[t] = W2[t];   // all 256 W2 values; visible after first loop-top sync

    int tx = t & 15, ty = t >> 4;   // tx -> j (with +16a), ty -> i (with +16b4)

    for (;;) {
        __syncthreads();                       // wsh visible / buffers & idsh reusable
        if (t == 0) idsh = atomicAdd(&c_steal, 1u);
        __syncthreads();
        unsigned id = idsh;
        if (id >= NTILE) break;

        int jT = (int)(id & 31) * TJ;
        int iT = (int)(id >> 5) * TI;

        u64 acc[8];
        #pragma unroll
        for (int p = 0; p < 8; p++) acc[p] = 0ull;

        // prefetch chunk 0 into buffer 0
        {
            // p=0: x rows (256 f4), p=1,2: y rows (512 f4)
            int row = t >> 3, c4 = t & 7;
            cpa16(&xbuf[0][row * SW + c4 * 4], &g_xp[(jT + row) * HD + c4 * 4]);
            #pragma unroll
            for (int p = 1; p < 3; p++) {
                int id2 = t + p * 256 - 256;   // 0..511
                int r2 = id2 >> 3, d4 = id2 & 7;
                cpa16(&ybuf[0][r2 * SW + d4 * 4], &g_yp[(iT + r2) * HD + d4 * 4]);
            }
            asm volatile("cp.async.commit_group;" ::: "memory");
        }

        #pragma unroll 1
        for (int ch = 0; ch < NCH; ch++) {
            if (ch < NCH - 1) {               // prefetch next chunk into other buffer
                int nb = (ch + 1) & 1;
                int ko = (ch + 1) * KC;
                int row = t >> 3, c4 = t & 7;
                cpa16(&xbuf[nb][row * SW + c4 * 4], &g_xp[(jT + row) * HD + ko + c4 * 4]);
                #pragma unroll
                for (int p = 1; p < 3; p++) {
                    int id2 = t + p * 256 - 256;
                    int r2 = id2 >> 3, d4 = id2 & 7;
                    cpa16(&ybuf[nb][r2 * SW + d4 * 4], &g_yp[(iT + r2) * HD + ko + d4 * 4]);
                }
                asm volatile("cp.async.commit_group;" ::: "memory");
                asm volatile("cp.async.wait_group 1;" ::: "memory");
            } else {
                asm volatile("cp.async.wait_group 0;" ::: "memory");
            }
            __syncthreads();

            const float* xb = xbuf[ch & 1];
            const float* yb = ybuf[ch & 1];

            #pragma unroll
            for (int j2 = 0; j2 < 8; j2++) {   // 4 k per iter
                ulonglong2 wv = *(const ulonglong2*)&wsh[ch * KC + j2 * 4];
                ulonglong2 xq[2], yq[4];
                #pragma unroll
                for (int a = 0; a < 2; a++)
                    xq[a] = *(const ulonglong2*)&xb[(tx + 16 * a) * SW + j2 * 4];
                #pragma unroll
                for (int b4 = 0; b4 < 4; b4++)
                    yq[b4] = *(const ulonglong2*)&yb[(ty + 16 * b4) * SW + j2 * 4];
                #pragma unroll
                for (int b4 = 0; b4 < 4; b4++) {
                    #pragma unroll
                    for (int a = 0; a < 2; a++) {
                        u64 s0 = add2(xq[a].x, yq[b4].x);
                        float l0, h0; up2(s0, l0, h0);
                        l0 = fmaxf(l0, 0.0f); h0 = fmaxf(h0, 0.0f);
                        acc[b4 * 2 + a] = fma2(pk2(l0, h0), wv.x, acc[b4 * 2 + a]);
                        u64 s1 = add2(xq[a].y, yq[b4].y);
                        float l1, h1; up2(s1, l1, h1);
                        l1 = fmaxf(l1, 0.0f); h1 = fmaxf(h1, 0.0f);
                        acc[b4 * 2 + a] = fma2(pk2(l1, h1), wv.y, acc[b4 * 2 + a]);
                    }
                }
            }
            __syncthreads();
        }

        // tile epilogue: dot values -> exp sum + diagonal
        float le = 0.0f, ld = 0.0f;
        #pragma unroll
        for (int b4 = 0; b4 < 4; b4++) {
            #pragma unroll
            for (int a = 0; a < 2; a++) {
                float lo, hi; up2(acc[b4 * 2 + a], lo, hi);
                float s = lo + hi;
                le += __expf(s);
                if (iT + ty + 16 * b4 == jT + tx + 16 * a) ld += s;
            }
        }
        #pragma unroll
        for (int o = 16; o > 0; o >>= 1) {
            le += __shfl_xor_sync(0xffffffffu, le, o);
            ld += __shfl_xor_sync(0xffffffffu, ld, o);
        }
        int wid = t >> 5, lane = t & 31;
        if (lane == 0) { rr[wid] = le; rr[8 + wid] = ld; }
        __syncthreads();
        if (t == 0) {
            float se = 0.0f, sd = 0.0f;
            #pragma unroll
            for (int w8 = 0; w8 < 8; w8++) { se += rr[w8]; sd += rr[8 + w8]; }
            g_pe[id] = (double)se;
            g_pd[id] = (double)sd;
        }
    }

    // ---------------- completion + final scalar ----------------
    __threadfence();
    __syncthreads();
    if (t == 0) {
        unsigned r = atomicAdd(&c_done, 1u);
        donesh = (r == (unsigned)(NCTA - 1)) ? 1 : 0;
    }
    __syncthreads();

    if (donesh) {
        __threadfence();
        double se = g_pe[t] + g_pe[t + 256];
        double sd = g_pd[t] + g_pd[t + 256];
        #pragma unroll
        for (int o = 16; o > 0; o >>= 1) {
            se += __shfl_xor_sync(0xffffffffu, se, o);
            sd += __shfl_xor_sync(0xffffffffu, sd, o);
        }
        int wid = t >> 5, lane = t & 31;
        if (lane == 0) { dr[wid] = se; dr[8 + wid] = sd; }
        __syncthreads();
        if (t == 0) {
            double tse = 0.0, tsd = 0.0;
            #pragma unroll
            for (int w8 = 0; w8 < 8; w8++) { tse += dr[w8]; tsd += dr[8 + w8]; }
            double bb = (double)b2[0];
            double lb = tsd / (double)NS + bb
                      - exp(bb - 1.0) * tse / ((double)NS * (double)NS);
            out[0] = (float)lb;
            // reset counters so graph replays start clean
            c_bar = 0u; c_steal = 0u; c_done = 0u;
        }
    }
}

extern "C" void kernel_launch(void* const* d_in, const int* in_sizes, int n_in,
                              void* d_out, int out_size)
{
    (void)in_sizes; (void)n_in; (void)out_size;
    const float* x  = (const float*)d_in[0];
    const float* y  = (const float*)d_in[1];
    const float* W1 = (const float*)d_in[2];
    const float* b1 = (const float*)d_in[3];
    const float* W2 = (const float*)d_in[4];
    const float* b2 = (const float*)d_in[5];

    k_fused<<<NCTA, 256>>>(x, y, W1, b1, W2, b2, (float*)d_out);
}

// round 6
// speedup vs baseline: 1.0995x; 1.0622x over previous
#include <cuda_runtime.h>
#include <math.h>

#define NS 1024
#define HD 256
#define XD 128
#define S2 34     // phase-2 smem row stride in float2 (68 words == 4 mod 8 -> conflict-free .128 quarters)
#define NCTA 256

// device scratch (no allocations allowed)
__device__ __align__(16) float g_xp[NS * HD];   // x @ Wx
__device__ __align__(16) float g_yp[NS * HD];   // y @ Wy + b1
__device__ double g_pe[NCTA];
__device__ double g_pd[NCTA];
__device__ unsigned int c_bar;    // phase barrier (0 at start; reset by final CTA)
__device__ unsigned int c_done;   // completion counter (ditto)

typedef unsigned long long u64;

__device__ __forceinline__ u64 pk2(float a, float b) {
    u64 r; asm("mov.b64 %0, {%1, %2};" : "=l"(r) : "f"(a), "f"(b)); return r;
}
__device__ __forceinline__ void up2(u64 v, float& a, float& b) {
    asm("mov.b64 {%0, %1}, %2;" : "=f"(a), "=f"(b) : "l"(v));
}
__device__ __forceinline__ u64 add2(u64 a, u64 b) {
    u64 r; asm("add.rn.f32x2 %0, %1, %2;" : "=l"(r) : "l"(a), "l"(b)); return r;
}
__device__ __forceinline__ u64 fma2(u64 a, u64 b, u64 c) {
    u64 r; asm("fma.rn.f32x2 %0, %1, %2, %3;" : "=l"(r) : "l"(a), "l"(b), "l"(c)); return r;
}

__global__ void __launch_bounds__(256, 2) k_fused(
    const float* __restrict__ x, const float* __restrict__ y,
    const float* __restrict__ W1, const float* __restrict__ b1,
    const float* __restrict__ W2, const float* __restrict__ b2,
    float* __restrict__ out)
{
    __shared__ __align__(16) float2 xsh[64 * S2];  // phase 2: j rows (phase 1 aliases this)
    __shared__ __align__(16) float2 ysh[64 * S2];  // phase 2: i rows
    __shared__ __align__(16) float2 wsh[128];      // all 256 W2 values
    __shared__ float rr[16];
    __shared__ double dr[16];
    __shared__ int donesh;

    int t = threadIdx.x;
    int cta = blockIdx.x;

    // ---------------- Phase 1: projections (8 rows per CTA) ----------------
    {
        float* xs = (float*)xsh;   // reuse phase-2 buffer: needs 128*10 floats = 5120 B
        int isY = cta >> 7;
        int row0 = (cta & 127) << 3;
        const float* src = isY ? y : x;
        const float* W = W1 + isY * (XD * HD);

        #pragma unroll
        for (int p = 0; p < 4; p++) {
            int idx = t + p * 256;          // 0..1023
            int r = idx >> 7, k = idx & 127;
            xs[k * 10 + r] = src[(row0 + r) * XD + k];
        }
        __syncthreads();

        u64 acc1[4];
        #pragma unroll
        for (int m = 0; m < 4; m++) acc1[m] = 0ull;

        #pragma unroll 8
        for (int k = 0; k < 128; k++) {
            float w = W[k * HD + t];
            u64 wd = pk2(w, w);
            #pragma unroll
            for (int m = 0; m < 4; m++)
                acc1[m] = fma2(*(const u64*)&xs[k * 10 + 2 * m], wd, acc1[m]);
        }

        float bias = isY ? b1[t] : 0.0f;
        float* dst = isY ? g_yp : g_xp;
        #pragma unroll
        for (int m = 0; m < 4; m++) {
            float v0, v1; up2(acc1[m], v0, v1);
            dst[(row0 + 2 * m)     * HD + t] = v0 + bias;
            dst[(row0 + 2 * m + 1) * HD + t] = v1 + bias;
        }
    }

    // ---------------- device-wide barrier ----------------
    __threadfence();
    __syncthreads();
    if (t == 0) {
        atomicAdd(&c_bar, 1u);
        while (atomicAdd(&c_bar, 0u) < (unsigned)NCTA) __nanosleep(128);
    }
    __syncthreads();
    __threadfence();

    // ---------------- Phase 2: one 64x64 pair tile per CTA (R2 config) ----------------
    if (t < 128) wsh[t] = ((const float2*)W2)[t];

    int tx = t & 15, ty = t >> 4;
    int jT = (cta & 15) << 6, iT = (cta >> 4) << 6;

    const float4* gx = (const float4*)g_xp;   // 64 f4 per 256-float row
    const float4* gy = (const float4*)g_yp;
    float4* xs4 = (float4*)xsh;               // 17 f4 per row (= S2 f2)
    float4* ys4 = (float4*)ysh;

    u64 acc[16];
    #pragma unroll
    for (int p = 0; p < 16; p++) acc[p] = 0ull;

    #pragma unroll 1
    for (int ch = 0; ch < 4; ch++) {
        __syncthreads();  // previous chunk reads done (and wsh/phase-1 alias safe on first pass)
        #pragma unroll
        for (int p = 0; p < 4; p++) {
            int idx = t + p * 256;            // 0..1023
            int row = idx >> 4, c4 = idx & 15;
            xs4[row * 17 + c4] = gx[(jT + row) * 64 + ch * 16 + c4];
            ys4[row * 17 + c4] = gy[(iT + row) * 64 + ch * 16 + c4];
        }
        __syncthreads();

        #pragma unroll 8
        for (int j2 = 0; j2 < 16; j2++) {     // 4 k per iter
            ulonglong2 wv = *(const ulonglong2*)&wsh[ch * 32 + 2 * j2];
            ulonglong2 xq[4], yq[4];
            #pragma unroll
            for (int a = 0; a < 4; a++)
                xq[a] = *(const ulonglong2*)&xsh[(tx + 16 * a) * S2 + 2 * j2];
            #pragma unroll
            for (int b4 = 0; b4 < 4; b4++)
                yq[b4] = *(const ulonglong2*)&ysh[(ty + 16 * b4) * S2 + 2 * j2];
            #pragma unroll
            for (int b4 = 0; b4 < 4; b4++) {
                #pragma unroll
                for (int a = 0; a < 4; a++) {
                    u64 t0 = add2(xq[a].x, yq[b4].x);
                    float l0, h0; up2(t0, l0, h0);
                    l0 = fmaxf(l0, 0.0f); h0 = fmaxf(h0, 0.0f);
                    acc[b4 * 4 + a] = fma2(pk2(l0, h0), wv.x, acc[b4 * 4 + a]);
                    u64 t1 = add2(xq[a].y, yq[b4].y);
                    float l1, h1; up2(t1, l1, h1);
                    l1 = fmaxf(l1, 0.0f); h1 = fmaxf(h1, 0.0f);
                    acc[b4 * 4 + a] = fma2(pk2(l1, h1), wv.y, acc[b4 * 4 + a]);
                }
            }
        }
    }

    // tile epilogue: per-pair dot -> exp-sum + diagonal capture
    float le = 0.0f, ld = 0.0f;
    #pragma unroll
    for (int b4 = 0; b4 < 4; b4++) {
        #pragma unroll
        for (int a = 0; a < 4; a++) {
            float lo, hi; up2(acc[b4 * 4 + a], lo, hi);
            float s = lo + hi;
            le += __expf(s);
            if (iT + ty + 16 * b4 == jT + tx + 16 * a) ld += s;
        }
    }

    #pragma unroll
    for (int o = 16; o > 0; o >>= 1) {
        le += __shfl_xor_sync(0xffffffffu, le, o);
        ld += __shfl_xor_sync(0xffffffffu, ld, o);
    }
    int wid = t >> 5, lane = t & 31;
    if (lane == 0) { rr[wid] = le; rr[8 + wid] = ld; }
    __syncthreads();
    if (t == 0) {
        float se = 0.0f, sd = 0.0f;
        #pragma unroll
        for (int w8 = 0; w8 < 8; w8++) { se += rr[w8]; sd += rr[8 + w8]; }
        g_pe[cta] = (double)se;
        g_pd[cta] = (double)sd;
    }

    // ---------------- completion + final scalar ----------------
    __threadfence();
    __syncthreads();
    if (t == 0) {
        unsigned r = atomicAdd(&c_done, 1u);
        donesh = (r == (unsigned)(NCTA - 1)) ? 1 : 0;
    }
    __syncthreads();

    if (donesh) {
        __threadfence();
        double se = g_pe[t];    // 256 threads, one partial each
        double sd = g_pd[t];
        #pragma unroll
        for (int o = 16; o > 0; o >>= 1) {
            se += __shfl_xor_sync(0xffffffffu, se, o);
            sd += __shfl_xor_sync(0xffffffffu, sd, o);
        }
        if (lane == 0) { dr[wid] = se; dr[8 + wid] = sd; }
        __syncthreads();
        if (t == 0) {
            double tse = 0.0, tsd = 0.0;
            #pragma unroll
            for (int w8 = 0; w8 < 8; w8++) { tse += dr[w8]; tsd += dr[8 + w8]; }
            double bb = (double)b2[0];
            double lb = tsd / (double)NS + bb
                      - exp(bb - 1.0) * tse / ((double)NS * (double)NS);
            out[0] = (float)lb;
            // reset counters so graph replays start clean
            c_bar = 0u; c_done = 0u;
        }
    }
}

extern "C" void kernel_launch(void* const* d_in, const int* in_sizes, int n_in,
                              void* d_out, int out_size)
{
    (void)in_sizes; (void)n_in; (void)out_size;
    const float* x  = (const float*)d_in[0];
    const float* y  = (const float*)d_in[1];
    const float* W1 = (const float*)d_in[2];
    const float* b1 = (const float*)d_in[3];
    const float* W2 = (const float*)d_in[4];
    const float* b2 = (const float*)d_in[5];

    k_fused<<<NCTA, 256>>>(x, y, W1, b1, W2, b2, (float*)d_out);
}

// round 7
// speedup vs baseline: 1.1533x; 1.0490x over previous
#include <cuda_runtime.h>
#include <math.h>

#define NS 1024
#define HD 256
#define XD 128
#define S2 34   // k_pair smem row stride in float2 units (conflict-free LDS.128 phases)

// scratch (device globals: no allocation allowed)
__device__ __align__(16) float g_xp[NS * HD];   // x @ Wx
__device__ __align__(16) float g_yp[NS * HD];   // y @ Wy + b1
__device__ double g_es;          // grand exp sum
__device__ double g_ds;          // diagonal sum
__device__ unsigned int g_cnt;   // k_pair completion counter

typedef unsigned long long u64;

__device__ __forceinline__ u64 pk2(float a, float b) {
    u64 r; asm("mov.b64 %0, {%1, %2};" : "=l"(r) : "f"(a), "f"(b)); return r;
}
__device__ __forceinline__ void up2(u64 v, float& a, float& b) {
    asm("mov.b64 {%0, %1}, %2;" : "=f"(a), "=f"(b) : "l"(v));
}
__device__ __forceinline__ u64 fma2(u64 a, u64 b, u64 c) {
    u64 r; asm("fma.rn.f32x2 %0, %1, %2, %3;" : "=l"(r) : "l"(a), "l"(b), "l"(c)); return r;
}

// fused: acc += relu(xv + yv) * w, all packed f32x2, one asm block so ptxas
// can keep lo/hi on the pair's own halves (no pack/unpack MOVs in SASS).
__device__ __forceinline__ void step(u64 xv, u64 yv, u64 w, u64& acc) {
    asm("{\n\t"
        ".reg .f32 lo, hi;\n\t"
        ".reg .b64 s;\n\t"
        "add.rn.f32x2 s, %1, %2;\n\t"
        "mov.b64 {lo, hi}, s;\n\t"
        "max.f32 lo, lo, 0f00000000;\n\t"
        "max.f32 hi, hi, 0f00000000;\n\t"
        "mov.b64 s, {lo, hi};\n\t"
        "fma.rn.f32x2 %0, s, %3, %0;\n\t"
        "}" : "+l"(acc) : "l"(xv), "l"(yv), "l"(w));
}

// xp = x @ W1[:128]; yp = y @ W1[128:] + b1.
// 128 blocks (SINGLE wave on 148 SMs) x 256 threads; 16 rows per block.
__global__ void __launch_bounds__(256) k_gemm(
    const float* __restrict__ x, const float* __restrict__ y,
    const float* __restrict__ W1, const float* __restrict__ b1)
{
    if (blockIdx.x == 0 && threadIdx.x == 0) { g_es = 0.0; g_ds = 0.0; g_cnt = 0u; }

    __shared__ __align__(16) float xs[128 * 18];  // [k][r], padded stride 18
    int b = blockIdx.x;
    int isY = b >> 6;
    int row0 = (b & 63) << 4;
    const float* src = isY ? y : x;
    const float* W = W1 + isY * (XD * HD);
    int t = threadIdx.x;

    #pragma unroll
    for (int p = 0; p < 8; p++) {
        int idx = t + p * 256;
        int r = idx >> 7, k = idx & 127;
        xs[k * 18 + r] = src[(row0 + r) * XD + k];
    }
    __syncthreads();

    u64 acc[8];
    #pragma unroll
    for (int m = 0; m < 8; m++) acc[m] = 0ull;

    #pragma unroll 8
    for (int k = 0; k < 128; k++) {
        float w = W[k * HD + t];
        u64 wd = pk2(w, w);
        #pragma unroll
        for (int m = 0; m < 8; m++)
            acc[m] = fma2(*(const u64*)&xs[k * 18 + 2 * m], wd, acc[m]);
    }

    float bias = isY ? b1[t] : 0.0f;
    float* dst = isY ? g_yp : g_xp;
    #pragma unroll
    for (int m = 0; m < 8; m++) {
        float v0, v1; up2(acc[m], v0, v1);
        dst[(row0 + 2 * m)     * HD + t] = v0 + bias;
        dst[(row0 + 2 * m + 1) * HD + t] = v1 + bias;
    }
}

// Pairwise kernel: 64x64 tile per CTA, 256 threads, thread = 4i x 4j, k packed x2.
// R2-proven config; inner step is the fused asm sequence. Last block folds scalar.
__global__ void __launch_bounds__(256, 2) k_pair(
    const float* __restrict__ W2, const float* __restrict__ b2,
    float* __restrict__ out)
{
    __shared__ __align__(16) float2 xsh[64 * S2];
    __shared__ __align__(16) float2 ysh[64 * S2];
    __shared__ __align__(16) float2 wsh[128];
    __shared__ float rr[16];

    int t = threadIdx.x;
    int tx = t & 15, ty = t >> 4;
    int jT = blockIdx.x << 6, iT = blockIdx.y << 6;

    if (t < 128) wsh[t] = ((const float2*)W2)[t];

    const float4* gx = (const float4*)g_xp;
    const float4* gy = (const float4*)g_yp;
    float4* xs4 = (float4*)xsh;   // 17 f4 per row
    float4* ys4 = (float4*)ysh;

    u64 acc[16];
    #pragma unroll
    for (int p = 0; p < 16; p++) acc[p] = 0ull;

    #pragma unroll 1
    for (int ch = 0; ch < 4; ch++) {
        __syncthreads();
        #pragma unroll
        for (int p = 0; p < 4; p++) {
            int idx = t + p * 256;
            int row = idx >> 4, c4 = idx & 15;
            xs4[row * 17 + c4] = gx[(jT + row) * 64 + ch * 16 + c4];
            ys4[row * 17 + c4] = gy[(iT + row) * 64 + ch * 16 + c4];
        }
        __syncthreads();

        #pragma unroll 8
        for (int j2 = 0; j2 < 16; j2++) {     // 4 k per iter
            ulonglong2 wv = *(const ulonglong2*)&wsh[ch * 32 + 2 * j2];
            ulonglong2 xq[4], yq[4];
            #pragma unroll
            for (int a = 0; a < 4; a++)
                xq[a] = *(const ulonglong2*)&xsh[(tx + 16 * a) * S2 + 2 * j2];
            #pragma unroll
            for (int b4 = 0; b4 < 4; b4++)
                yq[b4] = *(const ulonglong2*)&ysh[(ty + 16 * b4) * S2 + 2 * j2];
            #pragma unroll
            for (int b4 = 0; b4 < 4; b4++) {
                #pragma unroll
                for (int a = 0; a < 4; a++) {
                    step(xq[a].x, yq[b4].x, wv.x, acc[b4 * 4 + a]);
                    step(xq[a].y, yq[b4].y, wv.y, acc[b4 * 4 + a]);
                }
            }
        }
    }

    // epilogue: per-pair dot -> exp-sum + diagonal capture
    float le = 0.0f, ld = 0.0f;
    #pragma unroll
    for (int b4 = 0; b4 < 4; b4++) {
        #pragma unroll
        for (int a = 0; a < 4; a++) {
            float lo, hi; up2(acc[b4 * 4 + a], lo, hi);
            float s = lo + hi;
            le += __expf(s);
            if (iT + ty + 16 * b4 == jT + tx + 16 * a) ld += s;
        }
    }

    #pragma unroll
    for (int o = 16; o > 0; o >>= 1) {
        le += __shfl_xor_sync(0xffffffffu, le, o);
        ld += __shfl_xor_sync(0xffffffffu, ld, o);
    }
    int wid = t >> 5, lane = t & 31;
    if (lane == 0) { rr[wid] = le; rr[8 + wid] = ld; }
    __syncthreads();
    if (t == 0) {
        float se = 0.0f, sd = 0.0f;
        #pragma unroll
        for (int w8 = 0; w8 < 8; w8++) { se += rr[w8]; sd += rr[8 + w8]; }
        atomicAdd(&g_es, (double)se);
        if (iT == jT) atomicAdd(&g_ds, (double)sd);
        __threadfence();
        unsigned int c = atomicAdd(&g_cnt, 1u);
        if (c == 255u) {
            double es = atomicAdd(&g_es, 0.0);
            double ds = atomicAdd(&g_ds, 0.0);
            double bb = (double)b2[0];
            double lb = ds / (double)NS + bb
                      - exp(bb - 1.0) * es / ((double)NS * (double)NS);
            out[0] = (float)lb;
        }
    }
}

extern "C" void kernel_launch(void* const* d_in, const int* in_sizes, int n_in,
                              void* d_out, int out_size)
{
    (void)in_sizes; (void)n_in; (void)out_size;
    const float* x  = (const float*)d_in[0];
    const float* y  = (const float*)d_in[1];
    const float* W1 = (const float*)d_in[2];
    const float* b1 = (const float*)d_in[3];
    const float* W2 = (const float*)d_in[4];
    const float* b2 = (const float*)d_in[5];

    k_gemm<<<128, 256>>>(x, y, W1, b1);
    k_pair<<<dim3(16, 16), 256>>>(W2, b2, (float*)d_out);
}